// round 6
// baseline (speedup 1.0000x reference)
#include <cuda_runtime.h>
#include <cuda_bf16.h>
#include <cstdint>
#include <cstddef>

#define S 2048
#define E 1024
#define H 16
#define HD 64
#define SCALE 0.125f

// Scratch
__device__ float g_q[S * E];
__device__ float g_k[S * E];
__device__ float g_v[S * E];
__device__ float g_rel[S * S];
__device__ float g_attn[S * E];

// ---------------------------------------------------------------------------
// Helpers
// ---------------------------------------------------------------------------
__device__ __forceinline__ uint32_t smem_u32(const void* p) {
    uint32_t a;
    asm("{ .reg .u64 t; cvta.to.shared.u64 t, %1; cvt.u32.u64 %0, t; }"
        : "=r"(a) : "l"(p));
    return a;
}

__device__ __forceinline__ uint32_t sw128(uint32_t off) {
    return off ^ ((off >> 3) & 0x70);
}

__device__ __forceinline__ void ldsm4(uint32_t* r, uint32_t addr) {
    asm volatile("ldmatrix.sync.aligned.m8n8.x4.shared.b16 {%0,%1,%2,%3}, [%4];"
                 : "=r"(r[0]), "=r"(r[1]), "=r"(r[2]), "=r"(r[3]) : "r"(addr));
}

__device__ __forceinline__ void mma16816(float* c, const uint32_t* a, const uint32_t* b) {
    asm volatile(
        "mma.sync.aligned.m16n8k16.row.col.f32.bf16.bf16.f32 "
        "{%0,%1,%2,%3}, {%4,%5,%6,%7}, {%8,%9}, {%0,%1,%2,%3};"
        : "+f"(c[0]), "+f"(c[1]), "+f"(c[2]), "+f"(c[3])
        : "r"(a[0]), "r"(a[1]), "r"(a[2]), "r"(a[3]), "r"(b[0]), "r"(b[1]));
}

__device__ __forceinline__ uint32_t bf2(float lo, float hi) {
    uint32_t r;
    asm("cvt.rn.bf16x2.f32 %0, %1, %2;" : "=r"(r) : "f"(hi), "f"(lo));
    return r;
}

__device__ __forceinline__ void split2(float x, float y, uint32_t& hi, uint32_t& lo) {
    __nv_bfloat16 bx = __float2bfloat16(x), by = __float2bfloat16(y);
    __nv_bfloat162 hp; hp.x = bx; hp.y = by;
    hi = *(uint32_t*)&hp;
    lo = bf2(x - __bfloat162float(bx), y - __bfloat162float(by));
}

// Split fp32 pair -> bf16 hi/lo into SW128 row: [hi 32 bf16 | lo 32 bf16]
__device__ __forceinline__ void split_store_pair(char* base, int row, int col2,
                                                 float x0, float x1) {
    __nv_bfloat16 h0 = __float2bfloat16(x0);
    __nv_bfloat16 h1 = __float2bfloat16(x1);
    __nv_bfloat16 l0 = __float2bfloat16(x0 - __bfloat162float(h0));
    __nv_bfloat16 l1 = __float2bfloat16(x1 - __bfloat162float(h1));
    __nv_bfloat162 hp; hp.x = h0; hp.y = h1;
    __nv_bfloat162 lp; lp.x = l0; lp.y = l1;
    *(__nv_bfloat162*)(base + sw128(row * 128 + col2 * 2)) = hp;
    *(__nv_bfloat162*)(base + sw128(row * 128 + 64 + col2 * 2)) = lp;
}

__constant__ int c_aofs[3] = {0, 0, 32};
__constant__ int c_bofs[3] = {0, 32, 0};

// ---------------------------------------------------------------------------
// tc_gemm: C[M,N] = A[M,K]*B[N,K]^T (bf16x3). BM=128, BN=64, BK=32, 8 warps.
// Software pipelined: LDG of next chunk issued before MMA of current chunk.
// ---------------------------------------------------------------------------
__global__ __launch_bounds__(256) void tc_gemm(
    const float* __restrict__ A, const float* __restrict__ B,
    float* __restrict__ C, int K, int lda, int ldb, int ldc,
    const float* __restrict__ bias)
{
    __shared__ __align__(128) char smA[128 * 128];   // 16KB
    __shared__ __align__(128) char smB[64 * 128];    //  8KB

    const int tid = threadIdx.x;
    const int warp = tid >> 5, lane = tid & 31;
    const int row0 = blockIdx.y * 128;
    const int col0 = blockIdx.x * 64;
    const int wm0 = (warp >> 1) * 32;
    const int wn0 = (warp & 1) * 32;

    uint32_t sA = smem_u32(smA);
    uint32_t sB = smem_u32(smB);

    float c[2][4][4];
#pragma unroll
    for (int i = 0; i < 2; i++)
#pragma unroll
        for (int j = 0; j < 4; j++)
#pragma unroll
            for (int t = 0; t < 4; t++) c[i][j][t] = 0.f;

    // Prefetch regs
    float2 pa[8], pb[4];
#pragma unroll
    for (int s = 0; s < 8; s++) {
        int idx = s * 256 + tid;
        pa[s] = *(const float2*)&A[(size_t)(row0 + (idx >> 4)) * lda + 2 * (idx & 15)];
    }
#pragma unroll
    for (int s = 0; s < 4; s++) {
        int idx = s * 256 + tid;
        pb[s] = *(const float2*)&B[(size_t)(col0 + (idx >> 4)) * ldb + 2 * (idx & 15)];
    }

    const int arow = wm0 + (lane & 15);
    const int acolq = (lane >> 4) * 8;
    const int bn = wn0 + (lane & 7) + ((lane >> 4) << 3);
    const int bkq = ((lane >> 3) & 1) * 8;

    for (int k0 = 0; k0 < K; k0 += 32) {
        // STS current chunk
#pragma unroll
        for (int s = 0; s < 8; s++) {
            int idx = s * 256 + tid;
            split_store_pair(smA, idx >> 4, 2 * (idx & 15), pa[s].x, pa[s].y);
        }
#pragma unroll
        for (int s = 0; s < 4; s++) {
            int idx = s * 256 + tid;
            split_store_pair(smB, idx >> 4, 2 * (idx & 15), pb[s].x, pb[s].y);
        }
        __syncthreads();

        // LDG next chunk (overlaps MMA below)
        if (k0 + 32 < K) {
#pragma unroll
            for (int s = 0; s < 8; s++) {
                int idx = s * 256 + tid;
                pa[s] = *(const float2*)&A[(size_t)(row0 + (idx >> 4)) * lda +
                                           k0 + 32 + 2 * (idx & 15)];
            }
#pragma unroll
            for (int s = 0; s < 4; s++) {
                int idx = s * 256 + tid;
                pb[s] = *(const float2*)&B[(size_t)(col0 + (idx >> 4)) * ldb +
                                           k0 + 32 + 2 * (idx & 15)];
            }
        }

        // MMA on current chunk
#pragma unroll
        for (int s3 = 0; s3 < 3; s3++) {
            const int aoff = c_aofs[s3], boff = c_bofs[s3];
#pragma unroll
            for (int ks = 0; ks < 2; ks++) {
                int acol = aoff + ks * 16 + acolq;
                uint32_t a0[4], a1[4];
                ldsm4(a0, sA + sw128((uint32_t)(arow * 128 + acol * 2)));
                ldsm4(a1, sA + sw128((uint32_t)((arow + 16) * 128 + acol * 2)));
                int bcol = boff + ks * 16 + bkq;
                uint32_t bq[2][4];
#pragma unroll
                for (int j2 = 0; j2 < 2; j2++)
                    ldsm4(bq[j2], sB + sw128((uint32_t)((bn + j2 * 16) * 128 + bcol * 2)));
#pragma unroll
                for (int i = 0; i < 2; i++) {
                    const uint32_t* ai = (i == 0) ? a0 : a1;
#pragma unroll
                    for (int j = 0; j < 4; j++)
                        mma16816(c[i][j], ai, &bq[j >> 1][(j & 1) * 2]);
                }
            }
        }
        __syncthreads();
    }

    const int g = lane >> 2, t4 = lane & 3;
#pragma unroll
    for (int i = 0; i < 2; i++) {
#pragma unroll
        for (int j = 0; j < 4; j++) {
            int gr0 = row0 + wm0 + i * 16 + g;
            int gc = col0 + wn0 + j * 8 + t4 * 2;
            float v0 = c[i][j][0], v1 = c[i][j][1];
            float v2 = c[i][j][2], v3 = c[i][j][3];
            if (bias) {
                float2 bv = *(const float2*)&bias[gc];
                v0 += bv.x; v1 += bv.y; v2 += bv.x; v3 += bv.y;
            }
            *(float2*)&C[(size_t)gr0 * ldc + gc] = make_float2(v0, v1);
            *(float2*)&C[(size_t)(gr0 + 8) * ldc + gc] = make_float2(v2, v3);
        }
    }
}

// ---------------------------------------------------------------------------
// fused_attn (single pass, no max subtraction — scores bounded):
//   p = exp((q k^T + rel)*SCALE); w <- p (unnormalized); l += p; o += p*v
//   end: o /= l -> g_attn;  CTA rescales its own w rows by 1/l.
// 128 threads, 64 q-rows per CTA, grid (S/64, H). 64KB dyn smem.
// ---------------------------------------------------------------------------
__global__ __launch_bounds__(128) void fused_attn(
    const float* __restrict__ rel, float* __restrict__ wout)
{
    extern __shared__ char dyn[];
    char* skh = dyn;
    char* skl = dyn + 16384;
    char* svh = dyn + 32768;
    char* svl = dyn + 49152;

    const int tid = threadIdx.x;
    const int warp = tid >> 5, lane = tid & 31;
    const int g = lane >> 2, t4 = lane & 3;
    const int h = blockIdx.y;
    const int row0 = blockIdx.x * 64;
    const int qc0 = h * HD;

    const uint32_t uSkh = smem_u32(skh);
    const uint32_t uSkl = smem_u32(skl);
    const uint32_t uSvh = smem_u32(svh);
    const uint32_t uSvl = smem_u32(svl);

    const int rA = row0 + warp * 16 + g;
    const int rB = rA + 8;

    // q fragments
    uint32_t qh[4][4], ql[4][4];
#pragma unroll
    for (int ks = 0; ks < 4; ks++) {
        int c = qc0 + ks * 16 + 2 * t4;
        float2 x00 = *(const float2*)&g_q[(size_t)rA * E + c];
        float2 x10 = *(const float2*)&g_q[(size_t)rB * E + c];
        float2 x01 = *(const float2*)&g_q[(size_t)rA * E + c + 8];
        float2 x11 = *(const float2*)&g_q[(size_t)rB * E + c + 8];
        split2(x00.x, x00.y, qh[ks][0], ql[ks][0]);
        split2(x10.x, x10.y, qh[ks][1], ql[ks][1]);
        split2(x01.x, x01.y, qh[ks][2], ql[ks][2]);
        split2(x11.x, x11.y, qh[ks][3], ql[ks][3]);
    }

    const int lr = tid >> 4, lp = tid & 15;     // lr 0..7, lp 0..15
    const int bnp = (lane & 7) + ((lane >> 4) << 3);
    const int bkq = ((lane >> 3) & 1) * 8;

    float lA = 0.f, lB = 0.f;
    float o[8][4];
#pragma unroll
    for (int j = 0; j < 8; j++)
#pragma unroll
        for (int t = 0; t < 4; t++) o[j][t] = 0.f;

    float* wrow = wout + (size_t)h * S * S;

#pragma unroll 1
    for (int t0 = 0; t0 < S; t0 += 128) {
        __syncthreads();
#pragma unroll
        for (int s = 0; s < 16; s++) {
            int tr = s * 8 + lr;
            float4 kv = *(const float4*)&g_k[(size_t)(t0 + tr) * E + qc0 + 4 * lp];
            uint32_t h0, l0, h1, l1;
            split2(kv.x, kv.y, h0, l0);
            split2(kv.z, kv.w, h1, l1);
            *(uint2*)(skh + sw128(tr * 128 + 8 * lp)) = make_uint2(h0, h1);
            *(uint2*)(skl + sw128(tr * 128 + 8 * lp)) = make_uint2(l0, l1);

            float4 vv = *(const float4*)&g_v[(size_t)(t0 + tr) * E + qc0 + 4 * lp];
            int sub = tr >> 6, tc = tr & 63;
            char* bh_ = svh + sub * 8192;
            char* bl_ = svl + sub * 8192;
            float vs[4] = {vv.x, vv.y, vv.z, vv.w};
#pragma unroll
            for (int j = 0; j < 4; j++) {
                int d = 4 * lp + j;
                __nv_bfloat16 hb = __float2bfloat16(vs[j]);
                __nv_bfloat16 lb = __float2bfloat16(vs[j] - __bfloat162float(hb));
                *(__nv_bfloat16*)(bh_ + sw128(d * 128 + tc * 2)) = hb;
                *(__nv_bfloat16*)(bl_ + sw128(d * 128 + tc * 2)) = lb;
            }
        }
        __syncthreads();

#pragma unroll 1
        for (int ch = 0; ch < 8; ch++) {
            float cs[2][4];
#pragma unroll
            for (int i = 0; i < 2; i++)
#pragma unroll
                for (int t = 0; t < 4; t++) cs[i][t] = 0.f;
            int brow = ch * 16 + bnp;
#pragma unroll
            for (int ks = 0; ks < 4; ks++) {
                uint32_t bh[4], bl[4];
                uint32_t cb = (uint32_t)((ks * 16 + bkq) * 2);
                ldsm4(bh, uSkh + sw128(brow * 128 + cb));
                ldsm4(bl, uSkl + sw128(brow * 128 + cb));
                mma16816(cs[0], qh[ks], bh + 0);
                mma16816(cs[1], qh[ks], bh + 2);
                mma16816(cs[0], qh[ks], bl + 0);
                mma16816(cs[1], qh[ks], bl + 2);
                mma16816(cs[0], ql[ks], bh + 0);
                mma16816(cs[1], ql[ks], bh + 2);
            }
            int cg = t0 + ch * 16 + 2 * t4;
            float2 r00 = *(const float2*)&rel[(size_t)rA * S + cg];
            float2 r10 = *(const float2*)&rel[(size_t)rB * S + cg];
            float2 r01 = *(const float2*)&rel[(size_t)rA * S + cg + 8];
            float2 r11 = *(const float2*)&rel[(size_t)rB * S + cg + 8];
            float pA0 = __expf((cs[0][0] + r00.x) * SCALE);
            float pA1 = __expf((cs[0][1] + r00.y) * SCALE);
            float pA2 = __expf((cs[1][0] + r01.x) * SCALE);
            float pA3 = __expf((cs[1][1] + r01.y) * SCALE);
            float pB0 = __expf((cs[0][2] + r10.x) * SCALE);
            float pB1 = __expf((cs[0][3] + r10.y) * SCALE);
            float pB2 = __expf((cs[1][2] + r11.x) * SCALE);
            float pB3 = __expf((cs[1][3] + r11.y) * SCALE);

            // unnormalized writes
            *(float2*)&wrow[(size_t)rA * S + cg]     = make_float2(pA0, pA1);
            *(float2*)&wrow[(size_t)rA * S + cg + 8] = make_float2(pA2, pA3);
            *(float2*)&wrow[(size_t)rB * S + cg]     = make_float2(pB0, pB1);
            *(float2*)&wrow[(size_t)rB * S + cg + 8] = make_float2(pB2, pB3);

            lA += pA0 + pA1 + pA2 + pA3;
            lB += pB0 + pB1 + pB2 + pB3;

            // pack p as A-frag
            uint32_t ah[4], al[4];
            split2(pA0, pA1, ah[0], al[0]);
            split2(pB0, pB1, ah[1], al[1]);
            split2(pA2, pA3, ah[2], al[2]);
            split2(pB2, pB3, ah[3], al[3]);

            int sub = ch >> 2;
            uint32_t cb = (uint32_t)(((ch & 3) * 16 + bkq) * 2);
            uint32_t vbaseh = uSvh + sub * 8192;
            uint32_t vbasel = uSvl + sub * 8192;
#pragma unroll
            for (int jd = 0; jd < 4; jd++) {
                int dn = jd * 16 + bnp;
                uint32_t vh[4], vl[4];
                ldsm4(vh, vbaseh + sw128(dn * 128 + cb));
                ldsm4(vl, vbasel + sw128(dn * 128 + cb));
                mma16816(o[2 * jd],     ah, vh + 0);
                mma16816(o[2 * jd + 1], ah, vh + 2);
                mma16816(o[2 * jd],     ah, vl + 0);
                mma16816(o[2 * jd + 1], ah, vl + 2);
                mma16816(o[2 * jd],     al, vh + 0);
                mma16816(o[2 * jd + 1], al, vh + 2);
            }
        }
    }

    // finish row sums (quad reduce)
    lA += __shfl_xor_sync(0xffffffffu, lA, 1);
    lA += __shfl_xor_sync(0xffffffffu, lA, 2);
    lB += __shfl_xor_sync(0xffffffffu, lB, 1);
    lB += __shfl_xor_sync(0xffffffffu, lB, 2);
    const float invA = 1.f / lA, invB = 1.f / lB;

    // normalized attn output
#pragma unroll
    for (int j = 0; j < 8; j++) {
        int gc = qc0 + j * 8 + 2 * t4;
        *(float2*)&g_attn[(size_t)rA * E + gc] =
            make_float2(o[j][0] * invA, o[j][1] * invA);
        *(float2*)&g_attn[(size_t)rB * E + gc] =
            make_float2(o[j][2] * invB, o[j][3] * invB);
    }

    // rescale this CTA's w rows (each warp its 16 rows)
#pragma unroll 1
    for (int j = 0; j < 16; j++) {
        float inv = (j < 8) ? __shfl_sync(0xffffffffu, invA, 4 * j)
                            : __shfl_sync(0xffffffffu, invB, 4 * (j - 8));
        float4* p = (float4*)&wrow[(size_t)(row0 + warp * 16 + j) * S];
#pragma unroll 4
        for (int it = lane; it < S / 4; it += 32) {
            float4 v = p[it];
            v.x *= inv; v.y *= inv; v.z *= inv; v.w *= inv;
            p[it] = v;
        }
    }
}

// ---------------------------------------------------------------------------
// Launch
// ---------------------------------------------------------------------------
extern "C" void kernel_launch(void* const* d_in, const int* in_sizes, int n_in,
                              void* d_out, int out_size)
{
    (void)in_sizes; (void)n_in; (void)out_size;
    const float* query = (const float*)d_in[0];
    const float* key   = (const float*)d_in[1];
    const float* value = (const float*)d_in[2];
    const float* sim   = (const float*)d_in[3];
    const float* Wq    = (const float*)d_in[4];
    const float* bq    = (const float*)d_in[5];
    const float* Wk    = (const float*)d_in[6];
    const float* bk    = (const float*)d_in[7];
    const float* Wv    = (const float*)d_in[8];
    const float* bv    = (const float*)d_in[9];
    const float* Wo    = (const float*)d_in[10];
    const float* bo    = (const float*)d_in[11];

    float* out = (float*)d_out;                 // [S,E]
    float* w   = out + (size_t)S * E;           // [H,S,S]

    float *gq, *gk, *gv, *grel, *gattn;
    cudaGetSymbolAddress((void**)&gq,    g_q);
    cudaGetSymbolAddress((void**)&gk,    g_k);
    cudaGetSymbolAddress((void**)&gv,    g_v);
    cudaGetSymbolAddress((void**)&grel,  g_rel);
    cudaGetSymbolAddress((void**)&gattn, g_attn);

    static int attr_done = 0;
    if (!attr_done) {
        cudaFuncSetAttribute(fused_attn,
                             cudaFuncAttributeMaxDynamicSharedMemorySize, 65536);
        attr_done = 1;
    }

    dim3 blk(256);

    // Projections: q/k/v = X @ W^T + b   grid (1024/64, 2048/128) = (16,16)
    tc_gemm<<<dim3(E / 64, S / 128), blk>>>(query, Wq, gq, E, E, E, E, bq);
    tc_gemm<<<dim3(E / 64, S / 128), blk>>>(key,   Wk, gk, E, E, E, E, bk);
    tc_gemm<<<dim3(E / 64, S / 128), blk>>>(value, Wv, gv, E, E, E, E, bv);

    // rel = sim @ sim^T   grid (2048/64, 16) = (32,16)
    tc_gemm<<<dim3(S / 64, S / 128), blk>>>(sim, sim, grel, HD, HD, HD, S, nullptr);

    // fused attention (single pass): scores+exp+w write+PV+rescale
    fused_attn<<<dim3(S / 64, H), dim3(128), 65536>>>(grel, w);

    // out = attn @ Wo^T + bo
    tc_gemm<<<dim3(E / 64, S / 128), blk>>>(gattn, Wo, out, E, E, E, E, bo);
}

// round 7
// speedup vs baseline: 1.1481x; 1.1481x over previous
#include <cuda_runtime.h>
#include <cuda_bf16.h>
#include <cstdint>
#include <cstddef>

#define S 2048
#define E 1024
#define H 16
#define HD 64
#define NT 16              // S/128 k-tiles
#define SCALE 0.125f

// Scratch
__device__ float g_q[S * E];
__device__ float g_k[S * E];
__device__ float g_v[S * E];
__device__ float g_rel[S * S];      // pre-scaled by SCALE
__device__ float g_attn[S * E];
// Pre-split, pre-swizzled bf16 hi/lo tile images (exact smem byte layout)
__device__ __align__(128) char g_kt[H * NT * 32768];   // per tile: [hi 16KB][lo 16KB]
__device__ __align__(128) char g_vt[H * NT * 32768];   // per tile: [vhi 16KB][vlo 16KB]

// ---------------------------------------------------------------------------
// Helpers
// ---------------------------------------------------------------------------
__device__ __forceinline__ uint32_t smem_u32(const void* p) {
    uint32_t a;
    asm("{ .reg .u64 t; cvta.to.shared.u64 t, %1; cvt.u32.u64 %0, t; }"
        : "=r"(a) : "l"(p));
    return a;
}

__device__ __forceinline__ uint32_t sw128(uint32_t off) {
    return off ^ ((off >> 3) & 0x70);
}

__device__ __forceinline__ void ldsm4(uint32_t* r, uint32_t addr) {
    asm volatile("ldmatrix.sync.aligned.m8n8.x4.shared.b16 {%0,%1,%2,%3}, [%4];"
                 : "=r"(r[0]), "=r"(r[1]), "=r"(r[2]), "=r"(r[3]) : "r"(addr));
}

__device__ __forceinline__ void mma16816(float* c, const uint32_t* a, const uint32_t* b) {
    asm volatile(
        "mma.sync.aligned.m16n8k16.row.col.f32.bf16.bf16.f32 "
        "{%0,%1,%2,%3}, {%4,%5,%6,%7}, {%8,%9}, {%0,%1,%2,%3};"
        : "+f"(c[0]), "+f"(c[1]), "+f"(c[2]), "+f"(c[3])
        : "r"(a[0]), "r"(a[1]), "r"(a[2]), "r"(a[3]), "r"(b[0]), "r"(b[1]));
}

__device__ __forceinline__ uint32_t bf2(float lo, float hi) {
    uint32_t r;
    asm("cvt.rn.bf16x2.f32 %0, %1, %2;" : "=r"(r) : "f"(hi), "f"(lo));
    return r;
}

__device__ __forceinline__ void split2(float x, float y, uint32_t& hi, uint32_t& lo) {
    __nv_bfloat16 bx = __float2bfloat16(x), by = __float2bfloat16(y);
    __nv_bfloat162 hp; hp.x = bx; hp.y = by;
    hi = *(uint32_t*)&hp;
    lo = bf2(x - __bfloat162float(bx), y - __bfloat162float(by));
}

__device__ __forceinline__ void split_store_pair(char* base, int row, int col2,
                                                 float x0, float x1) {
    __nv_bfloat16 h0 = __float2bfloat16(x0);
    __nv_bfloat16 h1 = __float2bfloat16(x1);
    __nv_bfloat16 l0 = __float2bfloat16(x0 - __bfloat162float(h0));
    __nv_bfloat16 l1 = __float2bfloat16(x1 - __bfloat162float(h1));
    __nv_bfloat162 hp; hp.x = h0; hp.y = h1;
    __nv_bfloat162 lp; lp.x = l0; lp.y = l1;
    *(__nv_bfloat162*)(base + sw128(row * 128 + col2 * 2)) = hp;
    *(__nv_bfloat162*)(base + sw128(row * 128 + 64 + col2 * 2)) = lp;
}

#define CP16(dst, src) \
    asm volatile("cp.async.cg.shared.global [%0], [%1], 16;" :: "r"(dst), "l"(src))
#define CP_COMMIT() asm volatile("cp.async.commit_group;" ::: "memory")
#define CP_WAIT0()  asm volatile("cp.async.wait_group 0;" ::: "memory")

__constant__ int c_aofs[3] = {0, 0, 32};
__constant__ int c_bofs[3] = {0, 32, 0};

// ---------------------------------------------------------------------------
// tc_gemm (R5-proven): C[M,N] = (A[M,K]*B[N,K]^T)*cscale + bias
// BM=BN=128, BK=32, 8 warps.
// ---------------------------------------------------------------------------
__global__ __launch_bounds__(256) void tc_gemm(
    const float* __restrict__ A, const float* __restrict__ B,
    float* __restrict__ C, int K, int lda, int ldb, int ldc,
    const float* __restrict__ bias, float cscale)
{
    __shared__ __align__(128) char smA[128 * 128];
    __shared__ __align__(128) char smB[128 * 128];

    const int tid = threadIdx.x;
    const int warp = tid >> 5, lane = tid & 31;
    const int row0 = blockIdx.y * 128;
    const int col0 = blockIdx.x * 128;
    const int wm0 = (warp >> 1) * 32;
    const int wn0 = (warp & 1) * 64;

    uint32_t sA = smem_u32(smA);
    uint32_t sB = smem_u32(smB);

    float c[2][8][4];
#pragma unroll
    for (int i = 0; i < 2; i++)
#pragma unroll
        for (int j = 0; j < 8; j++)
#pragma unroll
            for (int t = 0; t < 4; t++) c[i][j][t] = 0.f;

    const int lr = tid >> 4;
    const int lp = tid & 15;

    for (int k0 = 0; k0 < K; k0 += 32) {
#pragma unroll
        for (int s = 0; s < 8; s++) {
            int r = s * 16 + lr;
            float2 va = *(const float2*)&A[(size_t)(row0 + r) * lda + k0 + 2 * lp];
            split_store_pair(smA, r, 2 * lp, va.x, va.y);
            float2 vb = *(const float2*)&B[(size_t)(col0 + r) * ldb + k0 + 2 * lp];
            split_store_pair(smB, r, 2 * lp, vb.x, vb.y);
        }
        __syncthreads();

        const int arow = wm0 + (lane & 15);
        const int acolq = (lane >> 4) * 8;
        const int bn = wn0 + (lane & 7) + ((lane >> 4) << 3);
        const int bkq = ((lane >> 3) & 1) * 8;

#pragma unroll
        for (int s3 = 0; s3 < 3; s3++) {
            const int aoff = c_aofs[s3], boff = c_bofs[s3];
#pragma unroll
            for (int ks = 0; ks < 2; ks++) {
                int acol = aoff + ks * 16 + acolq;
                uint32_t a0[4], a1[4];
                ldsm4(a0, sA + sw128((uint32_t)(arow * 128 + acol * 2)));
                ldsm4(a1, sA + sw128((uint32_t)((arow + 16) * 128 + acol * 2)));
                int bcol = boff + ks * 16 + bkq;
                uint32_t bq[4][4];
#pragma unroll
                for (int j2 = 0; j2 < 4; j2++)
                    ldsm4(bq[j2], sB + sw128((uint32_t)((bn + j2 * 16) * 128 + bcol * 2)));
#pragma unroll
                for (int i = 0; i < 2; i++) {
                    const uint32_t* ai = (i == 0) ? a0 : a1;
#pragma unroll
                    for (int j = 0; j < 8; j++)
                        mma16816(c[i][j], ai, &bq[j >> 1][(j & 1) * 2]);
                }
            }
        }
        __syncthreads();
    }

    const int g = lane >> 2, t4 = lane & 3;
#pragma unroll
    for (int i = 0; i < 2; i++) {
#pragma unroll
        for (int j = 0; j < 8; j++) {
            int gr0 = row0 + wm0 + i * 16 + g;
            int gc = col0 + wn0 + j * 8 + t4 * 2;
            float v0 = c[i][j][0] * cscale, v1 = c[i][j][1] * cscale;
            float v2 = c[i][j][2] * cscale, v3 = c[i][j][3] * cscale;
            if (bias) {
                float2 bv = *(const float2*)&bias[gc];
                v0 += bv.x; v1 += bv.y; v2 += bv.x; v3 += bv.y;
            }
            *(float2*)&C[(size_t)gr0 * ldc + gc] = make_float2(v0, v1);
            *(float2*)&C[(size_t)(gr0 + 8) * ldc + gc] = make_float2(v2, v3);
        }
    }
}

// ---------------------------------------------------------------------------
// prep_kv: split k/v into bf16 hi/lo pre-swizzled 32KB tile images.
// grid (NT, H), 128 threads.
// ---------------------------------------------------------------------------
__global__ __launch_bounds__(128) void prep_kv()
{
    const int tid = threadIdx.x;
    const int t0 = blockIdx.x * 128;
    const int h = blockIdx.y;
    const int qc0 = h * HD;
    char* kimg = g_kt + ((size_t)(h * NT + blockIdx.x)) * 32768;
    char* vimg = g_vt + ((size_t)(h * NT + blockIdx.x)) * 32768;

    const int lr = tid >> 4, lp = tid & 15;
#pragma unroll 4
    for (int s = 0; s < 16; s++) {
        int tr = s * 8 + lr;
        float4 kv = *(const float4*)&g_k[(size_t)(t0 + tr) * E + qc0 + 4 * lp];
        uint32_t h0, l0, h1, l1;
        split2(kv.x, kv.y, h0, l0);
        split2(kv.z, kv.w, h1, l1);
        *(uint2*)(kimg + sw128(tr * 128 + 8 * lp)) = make_uint2(h0, h1);
        *(uint2*)(kimg + 16384 + sw128(tr * 128 + 8 * lp)) = make_uint2(l0, l1);

        float4 vv = *(const float4*)&g_v[(size_t)(t0 + tr) * E + qc0 + 4 * lp];
        int sub = tr >> 6, tc = tr & 63;
        char* bh_ = vimg + sub * 8192;
        char* bl_ = vimg + 16384 + sub * 8192;
        float vs[4] = {vv.x, vv.y, vv.z, vv.w};
#pragma unroll
        for (int j = 0; j < 4; j++) {
            int d = 4 * lp + j;
            __nv_bfloat16 hb = __float2bfloat16(vs[j]);
            __nv_bfloat16 lb = __float2bfloat16(vs[j] - __bfloat162float(hb));
            *(__nv_bfloat16*)(bh_ + sw128(d * 128 + tc * 2)) = hb;
            *(__nv_bfloat16*)(bl_ + sw128(d * 128 + tc * 2)) = lb;
        }
    }
}

// ---------------------------------------------------------------------------
// fused_attn: 128 threads, 64 q-rows/CTA, grid (S/64, H).
// pass1 (double-buffered cp.async k): l = sum exp(q'k + rel')   [no max: bounded]
// pass2 (single-buffered cp.async k+v): w = exp(...)/l -> gmem; o += w*v
// q pre-scaled by SCALE at load; rel pre-scaled in gmem.
// ---------------------------------------------------------------------------
__global__ __launch_bounds__(128) void fused_attn(
    const float* __restrict__ rels, float* __restrict__ wout)
{
    extern __shared__ char dyn[];   // 64KB
    const uint32_t smb = smem_u32(dyn);

    const int tid = threadIdx.x;
    const int warp = tid >> 5, lane = tid & 31;
    const int g = lane >> 2, t4 = lane & 3;
    const int h = blockIdx.y;
    const int row0 = blockIdx.x * 64;
    const int qc0 = h * HD;

    const int rA = row0 + warp * 16 + g;
    const int rB = rA + 8;

    // q fragments, scaled by SCALE
    uint32_t qh[4][4], ql[4][4];
#pragma unroll
    for (int ks = 0; ks < 4; ks++) {
        int c = qc0 + ks * 16 + 2 * t4;
        float2 x00 = *(const float2*)&g_q[(size_t)rA * E + c];
        float2 x10 = *(const float2*)&g_q[(size_t)rB * E + c];
        float2 x01 = *(const float2*)&g_q[(size_t)rA * E + c + 8];
        float2 x11 = *(const float2*)&g_q[(size_t)rB * E + c + 8];
        split2(x00.x * SCALE, x00.y * SCALE, qh[ks][0], ql[ks][0]);
        split2(x10.x * SCALE, x10.y * SCALE, qh[ks][1], ql[ks][1]);
        split2(x01.x * SCALE, x01.y * SCALE, qh[ks][2], ql[ks][2]);
        split2(x11.x * SCALE, x11.y * SCALE, qh[ks][3], ql[ks][3]);
    }

    const int bnp = (lane & 7) + ((lane >> 4) << 3);
    const int bkq = ((lane >> 3) & 1) * 8;

    const char* ksrc = g_kt + ((size_t)h * NT) * 32768;
    const char* vsrc = g_vt + ((size_t)h * NT) * 32768;

    float lA = 0.f, lB = 0.f;

    // ===================== PASS 1: row sums =====================
    // stage tile 0 into buf0
#pragma unroll
    for (int i = 0; i < 16; i++) {
        uint32_t off = (uint32_t)(tid + i * 128) * 16;
        CP16(smb + off, ksrc + off);
    }
    CP_COMMIT();

#pragma unroll 1
    for (int t = 0; t < NT; t++) {
        CP_WAIT0();
        __syncthreads();
        if (t + 1 < NT) {
            const char* src = ksrc + (size_t)(t + 1) * 32768;
            uint32_t dst = smb + ((t + 1) & 1) * 32768;
#pragma unroll
            for (int i = 0; i < 16; i++) {
                uint32_t off = (uint32_t)(tid + i * 128) * 16;
                CP16(dst + off, src + off);
            }
            CP_COMMIT();
        }
        const uint32_t uSkh = smb + (t & 1) * 32768;
        const uint32_t uSkl = uSkh + 16384;

#pragma unroll 1
        for (int ch = 0; ch < 8; ch++) {
            float cs[2][4];
#pragma unroll
            for (int i = 0; i < 2; i++)
#pragma unroll
                for (int q2 = 0; q2 < 4; q2++) cs[i][q2] = 0.f;
            int brow = ch * 16 + bnp;
#pragma unroll
            for (int ks = 0; ks < 4; ks++) {
                uint32_t bh[4], bl[4];
                uint32_t cb = (uint32_t)((ks * 16 + bkq) * 2);
                ldsm4(bh, uSkh + sw128(brow * 128 + cb));
                ldsm4(bl, uSkl + sw128(brow * 128 + cb));
                mma16816(cs[0], qh[ks], bh + 0);
                mma16816(cs[1], qh[ks], bh + 2);
                mma16816(cs[0], qh[ks], bl + 0);
                mma16816(cs[1], qh[ks], bl + 2);
                mma16816(cs[0], ql[ks], bh + 0);
                mma16816(cs[1], ql[ks], bh + 2);
            }
            int cg = t * 128 + ch * 16 + 2 * t4;
            float2 r00 = *(const float2*)&rels[(size_t)rA * S + cg];
            float2 r10 = *(const float2*)&rels[(size_t)rB * S + cg];
            float2 r01 = *(const float2*)&rels[(size_t)rA * S + cg + 8];
            float2 r11 = *(const float2*)&rels[(size_t)rB * S + cg + 8];
            lA += __expf(cs[0][0] + r00.x) + __expf(cs[0][1] + r00.y) +
                  __expf(cs[1][0] + r01.x) + __expf(cs[1][1] + r01.y);
            lB += __expf(cs[0][2] + r10.x) + __expf(cs[0][3] + r10.y) +
                  __expf(cs[1][2] + r11.x) + __expf(cs[1][3] + r11.y);
        }
    }

    lA += __shfl_xor_sync(0xffffffffu, lA, 1);
    lA += __shfl_xor_sync(0xffffffffu, lA, 2);
    lB += __shfl_xor_sync(0xffffffffu, lB, 1);
    lB += __shfl_xor_sync(0xffffffffu, lB, 2);
    const float invA = 1.f / lA, invB = 1.f / lB;

    float o[8][4];
#pragma unroll
    for (int j = 0; j < 8; j++)
#pragma unroll
        for (int q2 = 0; q2 < 4; q2++) o[j][q2] = 0.f;

    float* wrow = wout + (size_t)h * S * S;

    // ===================== PASS 2: w + PV =====================
#pragma unroll 1
    for (int t = 0; t < NT; t++) {
        __syncthreads();   // prior reads of smem done
        {
            const char* src = ksrc + (size_t)t * 32768;
#pragma unroll
            for (int i = 0; i < 16; i++) {
                uint32_t off = (uint32_t)(tid + i * 128) * 16;
                CP16(smb + off, src + off);
            }
            const char* srcv = vsrc + (size_t)t * 32768;
#pragma unroll
            for (int i = 0; i < 16; i++) {
                uint32_t off = (uint32_t)(tid + i * 128) * 16;
                CP16(smb + 32768 + off, srcv + off);
            }
            CP_COMMIT();
            CP_WAIT0();
        }
        __syncthreads();
        const uint32_t uSkh = smb, uSkl = smb + 16384;
        const uint32_t uSvh = smb + 32768, uSvl = smb + 49152;

#pragma unroll 1
        for (int ch = 0; ch < 8; ch++) {
            float cs[2][4];
#pragma unroll
            for (int i = 0; i < 2; i++)
#pragma unroll
                for (int q2 = 0; q2 < 4; q2++) cs[i][q2] = 0.f;
            int brow = ch * 16 + bnp;
#pragma unroll
            for (int ks = 0; ks < 4; ks++) {
                uint32_t bh[4], bl[4];
                uint32_t cb = (uint32_t)((ks * 16 + bkq) * 2);
                ldsm4(bh, uSkh + sw128(brow * 128 + cb));
                ldsm4(bl, uSkl + sw128(brow * 128 + cb));
                mma16816(cs[0], qh[ks], bh + 0);
                mma16816(cs[1], qh[ks], bh + 2);
                mma16816(cs[0], qh[ks], bl + 0);
                mma16816(cs[1], qh[ks], bl + 2);
                mma16816(cs[0], ql[ks], bh + 0);
                mma16816(cs[1], ql[ks], bh + 2);
            }
            int cg = t * 128 + ch * 16 + 2 * t4;
            float2 r00 = *(const float2*)&rels[(size_t)rA * S + cg];
            float2 r10 = *(const float2*)&rels[(size_t)rB * S + cg];
            float2 r01 = *(const float2*)&rels[(size_t)rA * S + cg + 8];
            float2 r11 = *(const float2*)&rels[(size_t)rB * S + cg + 8];
            float wA0 = __expf(cs[0][0] + r00.x) * invA;
            float wA1 = __expf(cs[0][1] + r00.y) * invA;
            float wA2 = __expf(cs[1][0] + r01.x) * invA;
            float wA3 = __expf(cs[1][1] + r01.y) * invA;
            float wB0 = __expf(cs[0][2] + r10.x) * invB;
            float wB1 = __expf(cs[0][3] + r10.y) * invB;
            float wB2 = __expf(cs[1][2] + r11.x) * invB;
            float wB3 = __expf(cs[1][3] + r11.y) * invB;

            *(float2*)&wrow[(size_t)rA * S + cg]     = make_float2(wA0, wA1);
            *(float2*)&wrow[(size_t)rA * S + cg + 8] = make_float2(wA2, wA3);
            *(float2*)&wrow[(size_t)rB * S + cg]     = make_float2(wB0, wB1);
            *(float2*)&wrow[(size_t)rB * S + cg + 8] = make_float2(wB2, wB3);

            uint32_t ah[4], al[4];
            split2(wA0, wA1, ah[0], al[0]);
            split2(wB0, wB1, ah[1], al[1]);
            split2(wA2, wA3, ah[2], al[2]);
            split2(wB2, wB3, ah[3], al[3]);

            int sub = ch >> 2;
            uint32_t cb = (uint32_t)(((ch & 3) * 16 + bkq) * 2);
            uint32_t vbaseh = uSvh + sub * 8192;
            uint32_t vbasel = uSvl + sub * 8192;
#pragma unroll
            for (int jd = 0; jd < 4; jd++) {
                int dn = jd * 16 + bnp;
                uint32_t vh[4], vl[4];
                ldsm4(vh, vbaseh + sw128(dn * 128 + cb));
                ldsm4(vl, vbasel + sw128(dn * 128 + cb));
                mma16816(o[2 * jd],     ah, vh + 0);
                mma16816(o[2 * jd + 1], ah, vh + 2);
                mma16816(o[2 * jd],     ah, vl + 0);
                mma16816(o[2 * jd + 1], ah, vl + 2);
                mma16816(o[2 * jd],     al, vh + 0);
                mma16816(o[2 * jd + 1], al, vh + 2);
            }
        }
    }

    // epilogue: attn -> g_attn (already normalized)
#pragma unroll
    for (int j = 0; j < 8; j++) {
        int gc = qc0 + j * 8 + 2 * t4;
        *(float2*)&g_attn[(size_t)rA * E + gc] = make_float2(o[j][0], o[j][1]);
        *(float2*)&g_attn[(size_t)rB * E + gc] = make_float2(o[j][2], o[j][3]);
    }
}

// ---------------------------------------------------------------------------
// Launch
// ---------------------------------------------------------------------------
extern "C" void kernel_launch(void* const* d_in, const int* in_sizes, int n_in,
                              void* d_out, int out_size)
{
    (void)in_sizes; (void)n_in; (void)out_size;
    const float* query = (const float*)d_in[0];
    const float* key   = (const float*)d_in[1];
    const float* value = (const float*)d_in[2];
    const float* sim   = (const float*)d_in[3];
    const float* Wq    = (const float*)d_in[4];
    const float* bq    = (const float*)d_in[5];
    const float* Wk    = (const float*)d_in[6];
    const float* bk    = (const float*)d_in[7];
    const float* Wv    = (const float*)d_in[8];
    const float* bv    = (const float*)d_in[9];
    const float* Wo    = (const float*)d_in[10];
    const float* bo    = (const float*)d_in[11];

    float* out = (float*)d_out;                 // [S,E]
    float* w   = out + (size_t)S * E;           // [H,S,S]

    float *gq, *gk, *gv, *grel, *gattn;
    cudaGetSymbolAddress((void**)&gq,    g_q);
    cudaGetSymbolAddress((void**)&gk,    g_k);
    cudaGetSymbolAddress((void**)&gv,    g_v);
    cudaGetSymbolAddress((void**)&grel,  g_rel);
    cudaGetSymbolAddress((void**)&gattn, g_attn);

    static int attr_done = 0;
    if (!attr_done) {
        cudaFuncSetAttribute(fused_attn,
                             cudaFuncAttributeMaxDynamicSharedMemorySize, 65536);
        attr_done = 1;
    }

    dim3 blk(256);

    // Projections: q/k/v = X @ W^T + b
    tc_gemm<<<dim3(E / 128, S / 128), blk>>>(query, Wq, gq, E, E, E, E, bq, 1.f);
    tc_gemm<<<dim3(E / 128, S / 128), blk>>>(key,   Wk, gk, E, E, E, E, bk, 1.f);
    tc_gemm<<<dim3(E / 128, S / 128), blk>>>(value, Wv, gv, E, E, E, E, bv, 1.f);

    // rel = (sim @ sim^T) * SCALE  (pre-scaled for attention)
    tc_gemm<<<dim3(S / 128, S / 128), blk>>>(sim, sim, grel, HD, HD, HD, S, nullptr, SCALE);

    // pre-split k/v into swizzled bf16 tile images
    prep_kv<<<dim3(NT, H), dim3(128)>>>();

    // fused attention
    fused_attn<<<dim3(S / 64, H), dim3(128), 65536>>>(grel, w);

    // out = attn @ Wo^T + bo
    tc_gemm<<<dim3(E / 128, S / 128), blk>>>(gattn, Wo, out, E, E, E, E, bo, 1.f);
}